// round 2
// baseline (speedup 1.0000x reference)
#include <cuda_runtime.h>

#define T_STEPS 4096
#define RES     2048
#define NF      8
#define NO      8
#define GRID_B  128
#define BLOCK_B 256
#define NC      16     // output columns per CTA

// Scratch (allocation-free rule: device globals)
__device__ float g_drive[T_STEPS * RES];            // 32 MB
__device__ float g_X[T_STEPS * RES];                // 32 MB
__device__ unsigned int g_flag[GRID_B * 8];         // per-CTA step flags, 32B stride

__device__ __forceinline__ unsigned long long ffma2(unsigned long long a,
                                                    unsigned long long b,
                                                    unsigned long long c) {
    unsigned long long d;
    asm("fma.rn.f32x2 %0, %1, %2, %3;" : "=l"(d) : "l"(a), "l"(b), "l"(c));
    return d;
}
__device__ __forceinline__ unsigned long long pack2(float x, float y) {
    unsigned long long d;
    asm("mov.b64 %0, {%1, %2};" : "=l"(d) : "f"(x), "f"(y));
    return d;
}

// ---------------------------------------------------------------------------
// Kernel A: drive[t][r] = win_bias[r] + inp[t] @ win_u[:, r]   (+ flag reset)
// ---------------------------------------------------------------------------
__global__ void drive_kernel(const float* __restrict__ inp,
                             const float* __restrict__ Win) {
    int t = blockIdx.y;
    int r = blockIdx.x * blockDim.x + threadIdx.x;
    if (blockIdx.x == 0 && blockIdx.y == 0 && threadIdx.x < GRID_B)
        g_flag[threadIdx.x * 8] = 0u;
    float acc = Win[r];                       // bias row (Win[0])
#pragma unroll
    for (int f = 0; f < NF; f++)
        acc += inp[t * NF + f] * Win[(1 + f) * RES + r];
    g_drive[t * RES + r] = acc;
}

// ---------------------------------------------------------------------------
// Kernel B: persistent scan. 128 CTAs x 256 thr; each CTA owns 16 columns of
// W in registers. lane: col = lane&15, half = lane>>4. warp w covers
// i in [w*256, (w+1)*256); half h covers quads [i0 + h*128, i0+h*128+128).
// Sync: per-CTA release flags; each warp polls only its 16 producers.
// ---------------------------------------------------------------------------
__global__ void __launch_bounds__(BLOCK_B, 1)
scan_kernel(const float* __restrict__ W) {
    __shared__ float sx[RES];          // current x (8 KB)
    __shared__ float sred[8 * NC];     // per-warp partials

    const int tid  = threadIdx.x;
    const int w    = tid >> 5;
    const int lane = tid & 31;
    const int col  = lane & 15;
    const int half = lane >> 4;
    const int cbj  = blockIdx.x * NC;          // column base of this CTA
    const int jg   = cbj + col;                // global output column
    const int i0   = w * 256 + half * 128;     // this lane's 128-row chunk

    // --- one-time: load this lane's W slice (128 rows x 1 col) into registers
    unsigned long long wrA[32], wrB[32];
#pragma unroll
    for (int k = 0; k < 32; k++) {
        int i = i0 + 4 * k;
        wrA[k] = pack2(__ldg(&W[(size_t)i * RES + jg]),
                       __ldg(&W[(size_t)(i + 1) * RES + jg]));
        wrB[k] = pack2(__ldg(&W[(size_t)(i + 2) * RES + jg]),
                       __ldg(&W[(size_t)(i + 3) * RES + jg]));
    }

    for (int idx = tid; idx < RES; idx += BLOCK_B) sx[idx] = 0.0f;
    __syncthreads();

    const float4* sx4c = reinterpret_cast<const float4*>(sx);
    float4* sx4 = reinterpret_cast<float4*>(sx);
    const int qbase = i0 >> 2;

    const float dmp = 0.3f;
    const float omd = 1.0f - 0.3f;

    for (int t = 0; t < T_STEPS; t++) {
        // Prefetch drive + old-x for the 16 finalizer threads
        float drv = 0.0f, xold = 0.0f;
        if (tid < NC) {
            drv  = g_drive[t * RES + cbj + tid];
            xold = sx[cbj + tid];
        }

        // --- matvec partial: 32 broadcast LDS.128 + 64 fma.f32x2, 4 chains
        unsigned long long a0 = 0ull, a1 = 0ull, a2 = 0ull, a3 = 0ull;
#pragma unroll
        for (int k = 0; k < 32; k += 2) {
            float4 xq0 = sx4c[qbase + k];
            float4 xq1 = sx4c[qbase + k + 1];
            a0 = ffma2(wrA[k],     pack2(xq0.x, xq0.y), a0);
            a1 = ffma2(wrB[k],     pack2(xq0.z, xq0.w), a1);
            a2 = ffma2(wrA[k + 1], pack2(xq1.x, xq1.y), a2);
            a3 = ffma2(wrB[k + 1], pack2(xq1.z, xq1.w), a3);
        }
        float2 f0 = *reinterpret_cast<float2*>(&a0);
        float2 f1 = *reinterpret_cast<float2*>(&a1);
        float2 f2 = *reinterpret_cast<float2*>(&a2);
        float2 f3 = *reinterpret_cast<float2*>(&a3);
        float s = ((f0.x + f0.y) + (f1.x + f1.y)) +
                  ((f2.x + f2.y) + (f3.x + f3.y));
        s += __shfl_down_sync(0xffffffffu, s, 16);   // fold halves
        if (half == 0) sred[w * NC + col] = s;
        __syncthreads();                              // sync 1

        // --- finalize (warp 0, threads 0..15): 16 columns -> x_{t+1}
        if (w == 0) {
            if (tid < NC) {
                float tot = 0.0f;
#pragma unroll
                for (int ww = 0; ww < 8; ww++) tot += sred[ww * NC + tid];
                float xn = omd * xold + dmp * tanhf(drv + tot);
                g_X[(size_t)t * RES + cbj + tid] = xn;
            }
            if (t < T_STEPS - 1) {
                __syncwarp();
                if (tid == 0) {
                    unsigned step = (unsigned)(t + 1);
                    asm volatile("st.release.gpu.u32 [%0], %1;"
                                 :: "l"(&g_flag[blockIdx.x * 8]), "r"(step)
                                 : "memory");
                }
            }
        }
        if (t == T_STEPS - 1) break;

        // --- gather x_{t+1}: warp w owns slice [w*256, (w+1)*256) from
        //     producer CTAs [w*16, w*16+16). Poll flags, then load.
        {
            unsigned target = (unsigned)(t + 1);
            if (lane < 16) {
                const unsigned int* fp = &g_flag[(w * 16 + lane) * 8];
                unsigned v;
                do {
                    asm volatile("ld.acquire.gpu.u32 %0, [%1];"
                                 : "=r"(v) : "l"(fp) : "memory");
                } while (v < target);
            }
            __syncwarp();
            const float4* src =
                reinterpret_cast<const float4*>(&g_X[(size_t)t * RES]) + w * 64;
            float4 v0 = src[lane];
            float4 v1 = src[lane + 32];
            sx4[w * 64 + lane] = v0;
            sx4[w * 64 + 32 + lane] = v1;
        }
        __syncthreads();                              // sync 2
    }
}

// ---------------------------------------------------------------------------
// Kernel C: Y[t] = wout_bias + inp[t] @ wout_u + x_{t+1} @ wout_x
// ---------------------------------------------------------------------------
__global__ void readout_kernel(const float* __restrict__ inp,
                               const float* __restrict__ Wout,
                               float* __restrict__ out) {
    const int w    = threadIdx.x >> 5;
    const int lane = threadIdx.x & 31;
    const int t    = blockIdx.x * 8 + w;

    float acc[NO];
#pragma unroll
    for (int o = 0; o < NO; o++) acc[o] = 0.0f;

    const float* xrow = &g_X[(size_t)t * RES];
    for (int it = 0; it < RES / 32; it++) {
        int r = it * 32 + lane;
        float xv = xrow[r];
        const float4* wrow =
            reinterpret_cast<const float4*>(&Wout[(size_t)(1 + NF + r) * NO]);
        float4 wa = wrow[0], wb = wrow[1];
        acc[0] += xv * wa.x; acc[1] += xv * wa.y;
        acc[2] += xv * wa.z; acc[3] += xv * wa.w;
        acc[4] += xv * wb.x; acc[5] += xv * wb.y;
        acc[6] += xv * wb.z; acc[7] += xv * wb.w;
    }
#pragma unroll
    for (int o = 0; o < NO; o++) {
#pragma unroll
        for (int sft = 16; sft > 0; sft >>= 1)
            acc[o] += __shfl_down_sync(0xffffffffu, acc[o], sft);
    }
    if (lane == 0) {
#pragma unroll
        for (int o = 0; o < NO; o++) {
            float y = Wout[o];
#pragma unroll
            for (int f = 0; f < NF; f++)
                y += inp[t * NF + f] * Wout[(1 + f) * NO + o];
            out[t * NO + o] = y + acc[o];
        }
    }
}

// ---------------------------------------------------------------------------
extern "C" void kernel_launch(void* const* d_in, const int* in_sizes, int n_in,
                              void* d_out, int out_size) {
    const float* inp  = (const float*)d_in[0];   // (4096, 8)
    const float* Win  = (const float*)d_in[1];   // (9, 2048)
    const float* W    = (const float*)d_in[2];   // (2048, 2048)
    const float* Wout = (const float*)d_in[3];   // (2057, 8)
    float* out = (float*)d_out;                  // (4096, 8) fp32

    dim3 ga(RES / 256, T_STEPS);
    drive_kernel<<<ga, 256>>>(inp, Win);
    scan_kernel<<<GRID_B, BLOCK_B>>>(W);
    readout_kernel<<<T_STEPS / 8, 256>>>(inp, Wout, out);
}